// round 3
// baseline (speedup 1.0000x reference)
#include <cuda_runtime.h>
#include <math_constants.h>

// Problem constants
#define NUM_CODE 8192
#define CODE_DIM 256
#define HW       1024        // 32*32
#define NBATCH   16
#define NPTS     (NBATCH * HW)            // 16384 points
#define ZQ_ELEMS (NBATCH * CODE_DIM * HW) // 4194304

// Tiling
#define NSPLIT   8
#define CODES_PER_SPLIT (NUM_CODE / NSPLIT)  // 1024
#define PT_TILE  128
#define CT_TILE  128
#define DCHUNK   16
// zs: 256*128 floats, csm: 2*16*128 floats, z2s: 128 floats
#define SMEM_FLOATS (CODE_DIM * PT_TILE + 2 * DCHUNK * CT_TILE + PT_TILE)
#define SMEM_BYTES (SMEM_FLOATS * 4)   // 147968

// Scratch (device globals; no allocations allowed)
__device__ float g_pval[NSPLIT][NPTS];
__device__ int   g_pidx[NSPLIT][NPTS];
__device__ int   g_idx[NPTS];

// ---------------------------------------------------------------------------
// Main distance GEMM + running argmin.
// Block: 128 points x 1024 codes (one of 8 code splits).
// Score replicates the reference bitwise: s = fl(z2 - 2*dot)  (the +c2 term in
// the reference is provably a rounding no-op since c2 < ulp(score)/2), with
// first-occurrence (lowest index) tie-break at every reduction level.
// ---------------------------------------------------------------------------
__global__ __launch_bounds__(256)
void vq_main(const float* __restrict__ z_e, const float* __restrict__ cb) {
    extern __shared__ float smem[];
    float* zs  = smem;                       // [256][128]  (d-major, point-minor)
    float* csm = smem + CODE_DIM * PT_TILE;  // [2][16][128] (d-major, code-minor)
    float* z2s = csm + 2 * DCHUNK * CT_TILE; // [128] per-point squared norms

    const int tid = threadIdx.x;
    const int tx  = tid & 15;   // code group
    const int ty  = tid >> 4;   // point group
    const int p0  = blockIdx.x * PT_TILE;
    const int split = blockIdx.y;
    const int c_base = split * CODES_PER_SPLIT;

    // ---- load z tile: global layout is [b][d][hw] -> zs[d][p] (coalesced) ----
    {
        const int bimg = p0 >> 10;
        const int hw0  = p0 & 1023;
        const float* zbase = z_e + (size_t)bimg * (CODE_DIM * HW) + hw0;
        const int w  = tid >> 5;
        const int l4 = (tid & 31) << 2;
        #pragma unroll
        for (int it = 0; it < 32; ++it) {
            int d = it * 8 + w;
            *(float4*)&zs[d * PT_TILE + l4] = *(const float4*)&zbase[d * HW + l4];
        }
    }
    __syncthreads();

    // ---- per-point z2 from the smem tile (deterministic d order: identical
    //      across all splits so merge comparisons are consistent). Column
    //      reads have stride 128 floats -> bank = point -> conflict-free.
    if (tid < PT_TILE) {
        float s = 0.f;
        #pragma unroll 8
        for (int d = 0; d < CODE_DIM; ++d) {
            float v = zs[d * PT_TILE + tid];
            s = fmaf(v, v, s);
        }
        z2s[tid] = s;
    }
    __syncthreads();

    float z2r[8];
    #pragma unroll
    for (int i = 0; i < 4; ++i) {
        z2r[i]     = z2s[4 * ty + i];
        z2r[4 + i] = z2s[64 + 4 * ty + i];
    }

    float run_v[8];
    int   run_i[8];
    #pragma unroll
    for (int i = 0; i < 8; ++i) { run_v[i] = CUDART_INF_F; run_i[i] = 0x7fffffff; }

    const int dg = tid & 3;    // float4 slot along d within a 16-d chunk
    const int kk = tid >> 2;   // code 0..63 (plus +64 in second pass)

    for (int ct = 0; ct < CODES_PER_SPLIT / CT_TILE; ++ct) {
        const int k0 = c_base + ct * CT_TILE;
        const float* cbt = cb + (size_t)k0 * CODE_DIM;

        float acc[8][8];
        #pragma unroll
        for (int i = 0; i < 8; ++i)
            #pragma unroll
            for (int j = 0; j < 8; ++j) acc[i][j] = 0.f;

        // preload chunk 0
        float4 r0 = *(const float4*)&cbt[(size_t)kk * CODE_DIM + dg * 4];
        float4 r1 = *(const float4*)&cbt[(size_t)(kk + 64) * CODE_DIM + dg * 4];
        __syncthreads();  // prior csm reads done
        {
            float* dst = csm;  // buffer 0
            dst[(dg * 4 + 0) * CT_TILE + kk] = r0.x;
            dst[(dg * 4 + 1) * CT_TILE + kk] = r0.y;
            dst[(dg * 4 + 2) * CT_TILE + kk] = r0.z;
            dst[(dg * 4 + 3) * CT_TILE + kk] = r0.w;
            dst[(dg * 4 + 0) * CT_TILE + kk + 64] = r1.x;
            dst[(dg * 4 + 1) * CT_TILE + kk + 64] = r1.y;
            dst[(dg * 4 + 2) * CT_TILE + kk + 64] = r1.z;
            dst[(dg * 4 + 3) * CT_TILE + kk + 64] = r1.w;
        }
        __syncthreads();

        int cur = 0;
        #pragma unroll 1
        for (int ch = 0; ch < CODE_DIM / DCHUNK; ++ch) {
            float4 n0, n1;
            const bool more = (ch < CODE_DIM / DCHUNK - 1);
            if (more) {
                const float* src = cbt + (ch + 1) * DCHUNK;
                n0 = *(const float4*)&src[(size_t)kk * CODE_DIM + dg * 4];
                n1 = *(const float4*)&src[(size_t)(kk + 64) * CODE_DIM + dg * 4];
            }
            const float* cc = csm + cur * (DCHUNK * CT_TILE);
            #pragma unroll
            for (int dd = 0; dd < DCHUNK; ++dd) {
                const int d = ch * DCHUNK + dd;
                float4 zA = *(const float4*)&zs[d * PT_TILE + 4 * ty];
                float4 zB = *(const float4*)&zs[d * PT_TILE + 64 + 4 * ty];
                float4 cA = *(const float4*)&cc[dd * CT_TILE + 4 * tx];
                float4 cB = *(const float4*)&cc[dd * CT_TILE + 64 + 4 * tx];
                float zr[8] = {zA.x, zA.y, zA.z, zA.w, zB.x, zB.y, zB.z, zB.w};
                float cr[8] = {cA.x, cA.y, cA.z, cA.w, cB.x, cB.y, cB.z, cB.w};
                #pragma unroll
                for (int i = 0; i < 8; ++i)
                    #pragma unroll
                    for (int j = 0; j < 8; ++j)
                        acc[i][j] = fmaf(zr[i], cr[j], acc[i][j]);
            }
            if (more) {
                float* dst = csm + (cur ^ 1) * (DCHUNK * CT_TILE);
                dst[(dg * 4 + 0) * CT_TILE + kk] = n0.x;
                dst[(dg * 4 + 1) * CT_TILE + kk] = n0.y;
                dst[(dg * 4 + 2) * CT_TILE + kk] = n0.z;
                dst[(dg * 4 + 3) * CT_TILE + kk] = n0.w;
                dst[(dg * 4 + 0) * CT_TILE + kk + 64] = n1.x;
                dst[(dg * 4 + 1) * CT_TILE + kk + 64] = n1.y;
                dst[(dg * 4 + 2) * CT_TILE + kk + 64] = n1.z;
                dst[(dg * 4 + 3) * CT_TILE + kk + 64] = n1.w;
            }
            __syncthreads();
            cur ^= 1;
        }

        // ---- epilogue: quantized scores + argmin over this 128-code tile ----
        // s = fmaf(-2, dot, z2) == round(z2 - 2*dot) == reference's
        // fl(z2 - fl(2*M)) since 2*M is exact. The reference's +c2 is a no-op.
        #pragma unroll
        for (int i = 0; i < 8; ++i) {
            float bv = CUDART_INF_F;
            int bi = 0x7fffffff;
            #pragma unroll
            for (int j = 0; j < 8; ++j) {   // ascending code order; strict < keeps first
                int kidx = (j < 4) ? (k0 + 4 * tx + j) : (k0 + 64 + 4 * tx + (j - 4));
                float s = fmaf(-2.f, acc[i][j], z2r[i]);
                if (s < bv) { bv = s; bi = kidx; }
            }
            // reduce over the 16 tx-lanes sharing these 8 points
            #pragma unroll
            for (int o = 1; o < 16; o <<= 1) {
                float ov = __shfl_xor_sync(0xffffffffu, bv, o);
                int   oi = __shfl_xor_sync(0xffffffffu, bi, o);
                if (ov < bv || (ov == bv && oi < bi)) { bv = ov; bi = oi; }
            }
            if (bv < run_v[i] || (bv == run_v[i] && bi < run_i[i])) {
                run_v[i] = bv; run_i[i] = bi;
            }
        }
    }

    if (tx == 0) {
        #pragma unroll
        for (int i = 0; i < 8; ++i) {
            int p = (i < 4) ? (4 * ty + i) : (64 + 4 * ty + (i - 4));
            g_pval[split][p0 + p] = run_v[i];
            g_pidx[split][p0 + p] = run_i[i];
        }
    }
}

// ---------------------------------------------------------------------------
// Merge the 8 per-split partials (splits are ascending code ranges, so strict
// '<' preserves first-occurrence argmin). Also writes idx output (exact in f32).
// ---------------------------------------------------------------------------
__global__ void merge_kernel(float* __restrict__ out, int out_size) {
    int n = blockIdx.x * blockDim.x + threadIdx.x;
    if (n >= NPTS) return;
    float bv = g_pval[0][n];
    int   bi = g_pidx[0][n];
    #pragma unroll
    for (int s = 1; s < NSPLIT; ++s) {
        float v = g_pval[s][n];
        int   i = g_pidx[s][n];
        if (v < bv) { bv = v; bi = i; }
    }
    g_idx[n] = bi;
    if (out_size >= ZQ_ELEMS + NPTS)
        out[ZQ_ELEMS + n] = (float)bi;
}

// ---------------------------------------------------------------------------
// Gather z_q in NCHW with the reference's straight-through arithmetic
// (z + (zq - z)) to match its fp rounding exactly.
// ---------------------------------------------------------------------------
__global__ void gather_kernel(const float* __restrict__ z_e,
                              const float* __restrict__ cb,
                              float* __restrict__ out) {
    int o = blockIdx.x * 256 + threadIdx.x;   // 0..ZQ_ELEMS-1, coalesced writes
    int hw = o & 1023;
    int d  = (o >> 10) & 255;
    int b  = o >> 18;
    int n  = (b << 10) + hw;
    float zq = cb[(size_t)g_idx[n] * CODE_DIM + d];
    float zv = z_e[o];
    out[o] = zv + (zq - zv);
}

// ---------------------------------------------------------------------------
extern "C" void kernel_launch(void* const* d_in, const int* in_sizes, int n_in,
                              void* d_out, int out_size) {
    const float* z_e = (const float*)d_in[0];
    const float* cb  = (const float*)d_in[1];
    float* out = (float*)d_out;

    cudaFuncSetAttribute(vq_main, cudaFuncAttributeMaxDynamicSharedMemorySize,
                         SMEM_BYTES);

    dim3 grid(NPTS / PT_TILE, NSPLIT);
    vq_main<<<grid, 256, SMEM_BYTES>>>(z_e, cb);

    merge_kernel<<<(NPTS + 255) / 256, 256>>>(out, out_size);
    gather_kernel<<<ZQ_ELEMS / 256, 256>>>(z_e, cb, out);
}

// round 5
// speedup vs baseline: 1.1440x; 1.1440x over previous
#include <cuda_runtime.h>
#include <math_constants.h>

// Problem constants
#define NUM_CODE 8192
#define CODE_DIM 256
#define HW       1024        // 32*32
#define NBATCH   16
#define NPTS     (NBATCH * HW)            // 16384 points
#define ZQ_ELEMS (NBATCH * CODE_DIM * HW) // 4194304

// Tiling
#define NSPLIT   8
#define CODES_PER_SPLIT (NUM_CODE / NSPLIT)  // 1024
#define PT_TILE  128
#define CT_TILE  128
#define DCHUNK   16
// zs: 256*128 floats, csm: 2*16*128 floats, z2s: 128 floats
#define SMEM_FLOATS (CODE_DIM * PT_TILE + 2 * DCHUNK * CT_TILE + PT_TILE)
#define SMEM_BYTES (SMEM_FLOATS * 4)   // 147968

typedef unsigned long long ull;

// Packed fp32x2 FMA (Blackwell). Each 32-bit half is a bit-exact IEEE fp32
// FMA, so per-scalar accumulation order/rounding is identical to scalar FFMA.
__device__ __forceinline__ ull ffma2(ull a, ull b, ull c) {
    ull d;
    asm("fma.rn.f32x2 %0, %1, %2, %3;" : "=l"(d) : "l"(a), "l"(b), "l"(c));
    return d;
}
__device__ __forceinline__ ull pack2(float x, float y) {
    ull d;
    asm("mov.b64 %0, {%1, %2};" : "=l"(d) : "f"(x), "f"(y));
    return d;
}
__device__ __forceinline__ void unpack2(ull v, float& x, float& y) {
    asm("mov.b64 {%0, %1}, %2;" : "=f"(x), "=f"(y) : "l"(v));
}

// Scratch (device globals; no allocations allowed)
__device__ float g_pval[NSPLIT][NPTS];
__device__ int   g_pidx[NSPLIT][NPTS];
__device__ int   g_idx[NPTS];

// ---------------------------------------------------------------------------
// Main distance GEMM + running argmin.
// Block: 128 points x 1024 codes (one of 8 code splits). 256 threads,
// per-thread 8 points x 8 codes as 8x4 f32x2 accumulators.
// Score replicates the reference bitwise: s = fl(z2 - 2*dot); the +c2 term in
// the reference is a rounding no-op (c2 < ulp(score)/2). First-occurrence
// (lowest index) tie-break at every reduction level.
// ---------------------------------------------------------------------------
__global__ __launch_bounds__(256)
void vq_main(const float* __restrict__ z_e, const float* __restrict__ cb) {
    extern __shared__ float smem[];
    float* zs  = smem;                       // [256][128]  (d-major, point-minor)
    float* csm = smem + CODE_DIM * PT_TILE;  // [2][16][128] (d-major, code-minor)
    float* z2s = csm + 2 * DCHUNK * CT_TILE; // [128] per-point squared norms

    const int tid = threadIdx.x;
    const int tx  = tid & 15;   // code group
    const int ty  = tid >> 4;   // point group
    const int p0  = blockIdx.x * PT_TILE;
    const int split = blockIdx.y;
    const int c_base = split * CODES_PER_SPLIT;

    // ---- load z tile: global layout is [b][d][hw] -> zs[d][p] (coalesced) ----
    {
        const int bimg = p0 >> 10;
        const int hw0  = p0 & 1023;
        const float* zbase = z_e + (size_t)bimg * (CODE_DIM * HW) + hw0;
        const int w  = tid >> 5;
        const int l4 = (tid & 31) << 2;
        #pragma unroll
        for (int it = 0; it < 32; ++it) {
            int d = it * 8 + w;
            *(float4*)&zs[d * PT_TILE + l4] = *(const float4*)&zbase[d * HW + l4];
        }
    }
    __syncthreads();

    // ---- per-point z2 from the smem tile (deterministic d order: identical
    //      across all splits so merge comparisons are consistent).
    if (tid < PT_TILE) {
        float s = 0.f;
        #pragma unroll 8
        for (int d = 0; d < CODE_DIM; ++d) {
            float v = zs[d * PT_TILE + tid];
            s = fmaf(v, v, s);
        }
        z2s[tid] = s;
    }
    __syncthreads();

    float z2r[8];
    #pragma unroll
    for (int i = 0; i < 4; ++i) {
        z2r[i]     = z2s[4 * ty + i];
        z2r[4 + i] = z2s[64 + 4 * ty + i];
    }

    float run_v[8];
    int   run_i[8];
    #pragma unroll
    for (int i = 0; i < 8; ++i) { run_v[i] = CUDART_INF_F; run_i[i] = 0x7fffffff; }

    const int dg = tid & 3;    // float4 slot along d within a 16-d chunk
    const int kk = tid >> 2;   // code 0..63 (plus +64 in second pass)

    for (int ct = 0; ct < CODES_PER_SPLIT / CT_TILE; ++ct) {
        const int k0 = c_base + ct * CT_TILE;
        const float* cbt = cb + (size_t)k0 * CODE_DIM;

        // acc2[i][jp]: point i, code pair jp (jp0:{0,1} jp1:{2,3} of cA,
        // jp2:{0,1} jp3:{2,3} of cB). Halves are independent fp32 chains.
        ull acc2[8][4];
        #pragma unroll
        for (int i = 0; i < 8; ++i)
            #pragma unroll
            for (int j = 0; j < 4; ++j) acc2[i][j] = 0ull;

        // preload chunk 0
        float4 r0 = *(const float4*)&cbt[(size_t)kk * CODE_DIM + dg * 4];
        float4 r1 = *(const float4*)&cbt[(size_t)(kk + 64) * CODE_DIM + dg * 4];
        __syncthreads();  // prior csm reads done
        {
            float* dst = csm;  // buffer 0
            dst[(dg * 4 + 0) * CT_TILE + kk] = r0.x;
            dst[(dg * 4 + 1) * CT_TILE + kk] = r0.y;
            dst[(dg * 4 + 2) * CT_TILE + kk] = r0.z;
            dst[(dg * 4 + 3) * CT_TILE + kk] = r0.w;
            dst[(dg * 4 + 0) * CT_TILE + kk + 64] = r1.x;
            dst[(dg * 4 + 1) * CT_TILE + kk + 64] = r1.y;
            dst[(dg * 4 + 2) * CT_TILE + kk + 64] = r1.z;
            dst[(dg * 4 + 3) * CT_TILE + kk + 64] = r1.w;
        }
        __syncthreads();

        int cur = 0;
        #pragma unroll 1
        for (int ch = 0; ch < CODE_DIM / DCHUNK; ++ch) {
            float4 n0, n1;
            const bool more = (ch < CODE_DIM / DCHUNK - 1);
            if (more) {
                const float* src = cbt + (ch + 1) * DCHUNK;
                n0 = *(const float4*)&src[(size_t)kk * CODE_DIM + dg * 4];
                n1 = *(const float4*)&src[(size_t)(kk + 64) * CODE_DIM + dg * 4];
            }
            const float* cc = csm + cur * (DCHUNK * CT_TILE);
            #pragma unroll
            for (int dd = 0; dd < DCHUNK; ++dd) {
                const int d = ch * DCHUNK + dd;
                float4 zA = *(const float4*)&zs[d * PT_TILE + 4 * ty];
                float4 zB = *(const float4*)&zs[d * PT_TILE + 64 + 4 * ty];
                float4 cA = *(const float4*)&cc[dd * CT_TILE + 4 * tx];
                float4 cB = *(const float4*)&cc[dd * CT_TILE + 64 + 4 * tx];
                ull cp[4] = { pack2(cA.x, cA.y), pack2(cA.z, cA.w),
                              pack2(cB.x, cB.y), pack2(cB.z, cB.w) };
                float zr[8] = {zA.x, zA.y, zA.z, zA.w, zB.x, zB.y, zB.z, zB.w};
                #pragma unroll
                for (int i = 0; i < 8; ++i) {
                    ull zp = pack2(zr[i], zr[i]);
                    #pragma unroll
                    for (int j = 0; j < 4; ++j)
                        acc2[i][j] = ffma2(zp, cp[j], acc2[i][j]);
                }
            }
            if (more) {
                float* dst = csm + (cur ^ 1) * (DCHUNK * CT_TILE);
                dst[(dg * 4 + 0) * CT_TILE + kk] = n0.x;
                dst[(dg * 4 + 1) * CT_TILE + kk] = n0.y;
                dst[(dg * 4 + 2) * CT_TILE + kk] = n0.z;
                dst[(dg * 4 + 3) * CT_TILE + kk] = n0.w;
                dst[(dg * 4 + 0) * CT_TILE + kk + 64] = n1.x;
                dst[(dg * 4 + 1) * CT_TILE + kk + 64] = n1.y;
                dst[(dg * 4 + 2) * CT_TILE + kk + 64] = n1.z;
                dst[(dg * 4 + 3) * CT_TILE + kk + 64] = n1.w;
            }
            __syncthreads();
            cur ^= 1;
        }

        // ---- epilogue: quantized scores + argmin over this 128-code tile ----
        // Scan order per thread is ascending code index (jp 0,1 -> codes
        // 4tx..4tx+3; jp 2,3 -> +64), lo half before hi half, so strict '<'
        // keeps the first (lowest-index) minimum.
        #pragma unroll
        for (int i = 0; i < 8; ++i) {
            float bv = CUDART_INF_F;
            int bi = 0x7fffffff;
            #pragma unroll
            for (int jp = 0; jp < 4; ++jp) {
                float alo, ahi;
                unpack2(acc2[i][jp], alo, ahi);
                int kbase = (jp < 2) ? (k0 + 4 * tx + 2 * jp)
                                     : (k0 + 64 + 4 * tx + 2 * (jp - 2));
                float slo = fmaf(-2.f, alo, z2r[i]);
                float shi = fmaf(-2.f, ahi, z2r[i]);
                if (slo < bv) { bv = slo; bi = kbase; }
                if (shi < bv) { bv = shi; bi = kbase + 1; }
            }
            // reduce over the 16 tx-lanes sharing these 8 points
            #pragma unroll
            for (int o = 1; o < 16; o <<= 1) {
                float ov = __shfl_xor_sync(0xffffffffu, bv, o);
                int   oi = __shfl_xor_sync(0xffffffffu, bi, o);
                if (ov < bv || (ov == bv && oi < bi)) { bv = ov; bi = oi; }
            }
            if (bv < run_v[i] || (bv == run_v[i] && bi < run_i[i])) {
                run_v[i] = bv; run_i[i] = bi;
            }
        }
    }

    if (tx == 0) {
        #pragma unroll
        for (int i = 0; i < 8; ++i) {
            int p = (i < 4) ? (4 * ty + i) : (64 + 4 * ty + (i - 4));
            g_pval[split][p0 + p] = run_v[i];
            g_pidx[split][p0 + p] = run_i[i];
        }
    }
}

// ---------------------------------------------------------------------------
// Merge the 8 per-split partials (splits are ascending code ranges, so strict
// '<' preserves first-occurrence argmin). Also writes idx output (exact in f32).
// ---------------------------------------------------------------------------
__global__ void merge_kernel(float* __restrict__ out, int out_size) {
    int n = blockIdx.x * blockDim.x + threadIdx.x;
    if (n >= NPTS) return;
    float bv = g_pval[0][n];
    int   bi = g_pidx[0][n];
    #pragma unroll
    for (int s = 1; s < NSPLIT; ++s) {
        float v = g_pval[s][n];
        int   i = g_pidx[s][n];
        if (v < bv) { bv = v; bi = i; }
    }
    g_idx[n] = bi;
    if (out_size >= ZQ_ELEMS + NPTS)
        out[ZQ_ELEMS + n] = (float)bi;
}

// ---------------------------------------------------------------------------
// Gather z_q in NCHW with the reference's straight-through arithmetic
// (z + (zq - z)) to match its fp rounding exactly.
// ---------------------------------------------------------------------------
__global__ void gather_kernel(const float* __restrict__ z_e,
                              const float* __restrict__ cb,
                              float* __restrict__ out) {
    int o = blockIdx.x * 256 + threadIdx.x;   // 0..ZQ_ELEMS-1, coalesced writes
    int hw = o & 1023;
    int d  = (o >> 10) & 255;
    int b  = o >> 18;
    int n  = (b << 10) + hw;
    float zq = cb[(size_t)g_idx[n] * CODE_DIM + d];
    float zv = z_e[o];
    out[o] = zv + (zq - zv);
}

// ---------------------------------------------------------------------------
extern "C" void kernel_launch(void* const* d_in, const int* in_sizes, int n_in,
                              void* d_out, int out_size) {
    const float* z_e = (const float*)d_in[0];
    const float* cb  = (const float*)d_in[1];
    float* out = (float*)d_out;

    cudaFuncSetAttribute(vq_main, cudaFuncAttributeMaxDynamicSharedMemorySize,
                         SMEM_BYTES);

    dim3 grid(NPTS / PT_TILE, NSPLIT);
    vq_main<<<grid, 256, SMEM_BYTES>>>(z_e, cb);

    merge_kernel<<<(NPTS + 255) / 256, 256>>>(out, out_size);
    gather_kernel<<<ZQ_ELEMS / 256, 256>>>(z_e, cb, out);
}

// round 8
// speedup vs baseline: 1.2070x; 1.0551x over previous
#include <cuda_runtime.h>
#include <math_constants.h>

// Problem constants
#define NUM_CODE 8192
#define CODE_DIM 256
#define HW       1024        // 32*32
#define NBATCH   16
#define NPTS     (NBATCH * HW)            // 16384 points
#define ZQ_ELEMS (NBATCH * CODE_DIM * HW) // 4194304

// Tiling: block = 128 points x 256 codes, 512 threads, 8x8 per thread.
#define NSPLIT   8
#define CODES_PER_SPLIT (NUM_CODE / NSPLIT)  // 1024
#define PT_TILE  128
#define CT_TILE  256
#define DCHUNK   16
#define NTHREADS 512
// zs: 256*128 floats, csm: 2*16*256 floats, z2s: 128 floats
#define SMEM_FLOATS (CODE_DIM * PT_TILE + 2 * DCHUNK * CT_TILE + PT_TILE)
#define SMEM_BYTES (SMEM_FLOATS * 4)   // 164352

typedef unsigned long long ull;

// Packed fp32x2 FMA (Blackwell). Each 32-bit half is a bit-exact IEEE fp32
// FMA, so per-scalar accumulation order/rounding is identical to scalar FFMA.
// (Measured R5: same fma-pipe throughput as 2x FFMA, but halves issue slots.)
__device__ __forceinline__ ull ffma2(ull a, ull b, ull c) {
    ull d;
    asm("fma.rn.f32x2 %0, %1, %2, %3;" : "=l"(d) : "l"(a), "l"(b), "l"(c));
    return d;
}
__device__ __forceinline__ ull pack2(float x, float y) {
    ull d;
    asm("mov.b64 %0, {%1, %2};" : "=l"(d) : "f"(x), "f"(y));
    return d;
}
__device__ __forceinline__ void unpack2(ull v, float& x, float& y) {
    asm("mov.b64 {%0, %1}, %2;" : "=f"(x), "=f"(y) : "l"(v));
}

// Scratch (device globals; no allocations allowed)
__device__ float g_pval[NSPLIT][NPTS];
__device__ int   g_pidx[NSPLIT][NPTS];
__device__ int   g_idx[NPTS];

// ---------------------------------------------------------------------------
// Main distance GEMM + running argmin.
// Grid (128, 8): block handles 128 points x 1024 codes (one of 8 code splits)
// as 4 tiles of 256 codes. 512 threads (16 warps -> 4/SMSP for latency
// hiding), per-thread 8 points x 8 codes as 8x4 f32x2 accumulators.
// Score replicates the reference bitwise: s = fl(z2 - 2*dot); the +c2 term in
// the reference is a rounding no-op (c2 < ulp(score)/2). First-occurrence
// (lowest index) tie-break at every reduction level.
// ---------------------------------------------------------------------------
__global__ __launch_bounds__(NTHREADS)
void vq_main(const float* __restrict__ z_e, const float* __restrict__ cb) {
    extern __shared__ float smem[];
    float* zs  = smem;                       // [256][128]  (d-major, point-minor)
    float* csm = smem + CODE_DIM * PT_TILE;  // [2][16][256] (d-major, code-minor)
    float* z2s = csm + 2 * DCHUNK * CT_TILE; // [128] per-point squared norms

    const int tid = threadIdx.x;
    const int tx  = tid & 31;   // code group (0..31), uniform ty within a warp
    const int ty  = tid >> 5;   // point group (0..15)
    const int p0  = blockIdx.x * PT_TILE;
    const int split = blockIdx.y;
    const int c_base = split * CODES_PER_SPLIT;

    // ---- load z tile: global layout is [b][d][hw] -> zs[d][p] (coalesced) ----
    {
        const int bimg = p0 >> 10;
        const int hw0  = p0 & 1023;
        const float* zbase = z_e + (size_t)bimg * (CODE_DIM * HW) + hw0;
        const int w  = tid >> 5;              // 0..15
        const int l4 = (tid & 31) << 2;
        #pragma unroll
        for (int it = 0; it < 16; ++it) {
            int d = it * 16 + w;
            *(float4*)&zs[d * PT_TILE + l4] = *(const float4*)&zbase[d * HW + l4];
        }
    }
    __syncthreads();

    // ---- per-point z2 from the smem tile (deterministic ascending-d chain,
    //      identical across all splits so merge comparisons are consistent).
    if (tid < PT_TILE) {
        float s = 0.f;
        #pragma unroll 8
        for (int d = 0; d < CODE_DIM; ++d) {
            float v = zs[d * PT_TILE + tid];
            s = fmaf(v, v, s);
        }
        z2s[tid] = s;
    }
    __syncthreads();

    float z2r[8];
    #pragma unroll
    for (int i = 0; i < 4; ++i) {
        z2r[i]     = z2s[4 * ty + i];
        z2r[4 + i] = z2s[64 + 4 * ty + i];
    }

    float run_v[8];
    int   run_i[8];
    #pragma unroll
    for (int i = 0; i < 8; ++i) { run_v[i] = CUDART_INF_F; run_i[i] = 0x7fffffff; }

    const int dg = tid & 3;    // float4 slot along d within a 16-d chunk
    const int kk = tid >> 2;   // code 0..127 (plus +128 in second pass)

    for (int ct = 0; ct < CODES_PER_SPLIT / CT_TILE; ++ct) {
        const int k0 = c_base + ct * CT_TILE;
        const float* cbt = cb + (size_t)k0 * CODE_DIM;

        // acc2[i][jp]: point i, code pair jp (jp0:{0,1} jp1:{2,3} of cA,
        // jp2:{0,1} jp3:{2,3} of cB). Halves are independent fp32 chains.
        ull acc2[8][4];
        #pragma unroll
        for (int i = 0; i < 8; ++i)
            #pragma unroll
            for (int j = 0; j < 4; ++j) acc2[i][j] = 0ull;

        // preload chunk 0
        float4 r0 = *(const float4*)&cbt[(size_t)kk * CODE_DIM + dg * 4];
        float4 r1 = *(const float4*)&cbt[(size_t)(kk + 128) * CODE_DIM + dg * 4];
        __syncthreads();  // prior csm reads done
        {
            float* dst = csm;  // buffer 0
            dst[(dg * 4 + 0) * CT_TILE + kk] = r0.x;
            dst[(dg * 4 + 1) * CT_TILE + kk] = r0.y;
            dst[(dg * 4 + 2) * CT_TILE + kk] = r0.z;
            dst[(dg * 4 + 3) * CT_TILE + kk] = r0.w;
            dst[(dg * 4 + 0) * CT_TILE + kk + 128] = r1.x;
            dst[(dg * 4 + 1) * CT_TILE + kk + 128] = r1.y;
            dst[(dg * 4 + 2) * CT_TILE + kk + 128] = r1.z;
            dst[(dg * 4 + 3) * CT_TILE + kk + 128] = r1.w;
        }
        __syncthreads();

        int cur = 0;
        #pragma unroll 1
        for (int ch = 0; ch < CODE_DIM / DCHUNK; ++ch) {
            float4 n0, n1;
            const bool more = (ch < CODE_DIM / DCHUNK - 1);
            if (more) {
                const float* src = cbt + (ch + 1) * DCHUNK;
                n0 = *(const float4*)&src[(size_t)kk * CODE_DIM + dg * 4];
                n1 = *(const float4*)&src[(size_t)(kk + 128) * CODE_DIM + dg * 4];
            }
            const float* cc = csm + cur * (DCHUNK * CT_TILE);
            #pragma unroll
            for (int dd = 0; dd < DCHUNK; ++dd) {
                const int d = ch * DCHUNK + dd;
                float4 zA = *(const float4*)&zs[d * PT_TILE + 4 * ty];
                float4 zB = *(const float4*)&zs[d * PT_TILE + 64 + 4 * ty];
                // code pairs loaded directly as 64-bit lanes (16B aligned):
                // no pack movs needed for the multiplier operands.
                ulonglong2 cAp = *(const ulonglong2*)&cc[dd * CT_TILE + 4 * tx];
                ulonglong2 cBp = *(const ulonglong2*)&cc[dd * CT_TILE + 128 + 4 * tx];
                ull cp[4] = { cAp.x, cAp.y, cBp.x, cBp.y };
                float zr[8] = {zA.x, zA.y, zA.z, zA.w, zB.x, zB.y, zB.z, zB.w};
                #pragma unroll
                for (int i = 0; i < 8; ++i) {
                    ull zp = pack2(zr[i], zr[i]);
                    #pragma unroll
                    for (int j = 0; j < 4; ++j)
                        acc2[i][j] = ffma2(zp, cp[j], acc2[i][j]);
                }
            }
            if (more) {
                float* dst = csm + (cur ^ 1) * (DCHUNK * CT_TILE);
                dst[(dg * 4 + 0) * CT_TILE + kk] = n0.x;
                dst[(dg * 4 + 1) * CT_TILE + kk] = n0.y;
                dst[(dg * 4 + 2) * CT_TILE + kk] = n0.z;
                dst[(dg * 4 + 3) * CT_TILE + kk] = n0.w;
                dst[(dg * 4 + 0) * CT_TILE + kk + 128] = n1.x;
                dst[(dg * 4 + 1) * CT_TILE + kk + 128] = n1.y;
                dst[(dg * 4 + 2) * CT_TILE + kk + 128] = n1.z;
                dst[(dg * 4 + 3) * CT_TILE + kk + 128] = n1.w;
            }
            __syncthreads();
            cur ^= 1;
        }

        // ---- epilogue: quantized scores + argmin over this 256-code tile ----
        // Per-thread scan is ascending code index (jp 0,1 -> codes 4tx..4tx+3;
        // jp 2,3 -> +128), lo half before hi half: strict '<' keeps the first
        // (lowest-index) minimum. Cross-lane reduce is index-tie-broken.
        #pragma unroll
        for (int i = 0; i < 8; ++i) {
            float bv = CUDART_INF_F;
            int bi = 0x7fffffff;
            #pragma unroll
            for (int jp = 0; jp < 4; ++jp) {
                float alo, ahi;
                unpack2(acc2[i][jp], alo, ahi);
                int kbase = (jp < 2) ? (k0 + 4 * tx + 2 * jp)
                                     : (k0 + 128 + 4 * tx + 2 * (jp - 2));
                float slo = fmaf(-2.f, alo, z2r[i]);
                float shi = fmaf(-2.f, ahi, z2r[i]);
                if (slo < bv) { bv = slo; bi = kbase; }
                if (shi < bv) { bv = shi; bi = kbase + 1; }
            }
            // reduce over the 32 tx-lanes (full warp, uniform ty)
            #pragma unroll
            for (int o = 1; o < 32; o <<= 1) {
                float ov = __shfl_xor_sync(0xffffffffu, bv, o);
                int   oi = __shfl_xor_sync(0xffffffffu, bi, o);
                if (ov < bv || (ov == bv && oi < bi)) { bv = ov; bi = oi; }
            }
            if (bv < run_v[i] || (bv == run_v[i] && bi < run_i[i])) {
                run_v[i] = bv; run_i[i] = bi;
            }
        }
    }

    if (tx == 0) {
        #pragma unroll
        for (int i = 0; i < 8; ++i) {
            int p = (i < 4) ? (4 * ty + i) : (64 + 4 * ty + (i - 4));
            g_pval[split][p0 + p] = run_v[i];
            g_pidx[split][p0 + p] = run_i[i];
        }
    }
}

// ---------------------------------------------------------------------------
// Merge the 8 per-split partials (splits are ascending code ranges, so strict
// '<' preserves first-occurrence argmin). Also writes idx output (exact in f32).
// ---------------------------------------------------------------------------
__global__ void merge_kernel(float* __restrict__ out, int out_size) {
    int n = blockIdx.x * blockDim.x + threadIdx.x;
    if (n >= NPTS) return;
    float bv = g_pval[0][n];
    int   bi = g_pidx[0][n];
    #pragma unroll
    for (int s = 1; s < NSPLIT; ++s) {
        float v = g_pval[s][n];
        int   i = g_pidx[s][n];
        if (v < bv) { bv = v; bi = i; }
    }
    g_idx[n] = bi;
    if (out_size >= ZQ_ELEMS + NPTS)
        out[ZQ_ELEMS + n] = (float)bi;
}

// ---------------------------------------------------------------------------
// Gather z_q in NCHW with the reference's straight-through arithmetic
// (z + (zq - z)) to match its fp rounding exactly.
// ---------------------------------------------------------------------------
__global__ void gather_kernel(const float* __restrict__ z_e,
                              const float* __restrict__ cb,
                              float* __restrict__ out) {
    int o = blockIdx.x * 256 + threadIdx.x;   // 0..ZQ_ELEMS-1, coalesced writes
    int hw = o & 1023;
    int d  = (o >> 10) & 255;
    int b  = o >> 18;
    int n  = (b << 10) + hw;
    float zq = cb[(size_t)g_idx[n] * CODE_DIM + d];
    float zv = z_e[o];
    out[o] = zv + (zq - zv);
}

// ---------------------------------------------------------------------------
extern "C" void kernel_launch(void* const* d_in, const int* in_sizes, int n_in,
                              void* d_out, int out_size) {
    const float* z_e = (const float*)d_in[0];
    const float* cb  = (const float*)d_in[1];
    float* out = (float*)d_out;

    cudaFuncSetAttribute(vq_main, cudaFuncAttributeMaxDynamicSharedMemorySize,
                         SMEM_BYTES);

    dim3 grid(NPTS / PT_TILE, NSPLIT);
    vq_main<<<grid, NTHREADS, SMEM_BYTES>>>(z_e, cb);

    merge_kernel<<<(NPTS + 255) / 256, 256>>>(out, out_size);
    gather_kernel<<<ZQ_ELEMS / 256, 256>>>(z_e, cb, out);
}